// round 3
// baseline (speedup 1.0000x reference)
#include <cuda_runtime.h>

#define B_   256
#define M_   8
#define L_   64
#define E_   128
#define H_   8
#define HD_  16
#define QKV_ 384
#define R_   (B_ * M_)   // 2048 rows

// Scratch (no allocation allowed -> __device__ globals)
__device__ float g_agg0[R_ * E_];        // mean-fused walk aggregate, row = b*8+m
__device__ float g_agg1[R_ * E_];        // after per-metapath linear
__device__ float g_qkv[R_ * QKV_];       // qkv projection, row = b*8+m
__device__ float g_o[R_ * E_];           // attention head output
__device__ float g_WqkvT[E_ * QKV_];     // Wqkv transposed: [e][j]
__device__ float g_WoT[E_ * E_];         // Wo transposed:   [e][j]

// ---------------------------------------------------------------------------
// Kernel T: transpose Wqkv [384][128] -> [128][384], Wo [128][128] -> [128][128]
// ---------------------------------------------------------------------------
__global__ void k_transpose(const float* __restrict__ Wqkv,
                            const float* __restrict__ Wo) {
    int tid = blockIdx.x * blockDim.x + threadIdx.x;
    if (tid < E_ * QKV_) {
        int j = tid / E_;
        int e = tid % E_;
        g_WqkvT[e * QKV_ + j] = Wqkv[j * E_ + e];
    }
    if (tid < E_ * E_) {
        int j = tid / E_;
        int e = tid % E_;
        g_WoT[e * E_ + j] = Wo[j * E_ + e];
    }
}

// ---------------------------------------------------------------------------
// Kernel A: gather + elementwise fuse + mean over walk steps
// block = (b*M + m), thread = e.
// ---------------------------------------------------------------------------
__global__ void k_gather(const int*   __restrict__ walks,
                         const float* __restrict__ node_table,
                         const float* __restrict__ fc1_b,
                         const float* __restrict__ edge_table) {
    __shared__ int s_idx[L_ * 3];
    const int bid = blockIdx.x;
    const int tid = threadIdx.x;
    const int base = bid * (L_ * 3);
    for (int i = tid; i < L_ * 3; i += E_) s_idx[i] = walks[base + i];
    __syncthreads();

    const float fb = fc1_b[tid];
    float acc = 0.f;
#pragma unroll 8
    for (int l = 0; l < L_; l++) {
        int n1 = s_idx[3 * l + 0];
        int n2 = s_idx[3 * l + 1];
        int et = s_idx[3 * l + 2];
        float a = node_table[n1 * E_ + tid] + fb;
        float b = node_table[n2 * E_ + tid] + fb;
        float c = edge_table[et * E_ + tid];
        acc += a * b * c;
    }
    g_agg0[bid * E_ + tid] = acc * (1.f / (float)L_);
}

// ---------------------------------------------------------------------------
// Kernel B: per-metapath linear, GEMM-style.
// block = (m, 16-batch tile); 256 threads = 128 cols x 2 rowgroups of 8.
// X staged transposed in smem -> broadcast LDS.128, weight LDG amortized x8.
// ---------------------------------------------------------------------------
__global__ void __launch_bounds__(256) k_mplinear(const int*   __restrict__ mp_type_idx,
                                                  const float* __restrict__ W_mp,
                                                  const float* __restrict__ b_mp) {
    __shared__ __align__(16) float s_xT[E_][20];   // 16 rows + pad
    const int m   = blockIdx.x;
    const int b0  = blockIdx.y * 16;
    const int tid = threadIdx.x;
    const int j   = tid & 127;
    const int rg  = tid >> 7;        // 0/1 -> rows rg*8 .. rg*8+7

    for (int i = tid; i < 16 * E_; i += 256) {
        int row = i >> 7;
        int e   = i & 127;
        s_xT[e][row] = g_agg0[((b0 + row) * M_ + m) * E_ + e];
    }
    __syncthreads();

    const int mt = mp_type_idx[m];
    const float* W = W_mp + mt * (E_ * E_);
    const float bv = b_mp[mt * E_ + j];

    float acc[8];
#pragma unroll
    for (int i = 0; i < 8; i++) acc[i] = bv;

#pragma unroll 4
    for (int e = 0; e < E_; e++) {
        float w = W[e * E_ + j];
        float4 x0 = *reinterpret_cast<const float4*>(&s_xT[e][rg * 8 + 0]);
        float4 x1 = *reinterpret_cast<const float4*>(&s_xT[e][rg * 8 + 4]);
        acc[0] += x0.x * w; acc[1] += x0.y * w; acc[2] += x0.z * w; acc[3] += x0.w * w;
        acc[4] += x1.x * w; acc[5] += x1.y * w; acc[6] += x1.z * w; acc[7] += x1.w * w;
    }
#pragma unroll
    for (int i = 0; i < 8; i++)
        g_agg1[((b0 + rg * 8 + i) * M_ + m) * E_ + j] = acc[i];
}

// ---------------------------------------------------------------------------
// Kernel C: QKV GEMM  [2048,128] @ [128,384].
// grid = (64 row-tiles of 32, 3 col-tiles of 128); 256 threads.
// ---------------------------------------------------------------------------
__global__ void __launch_bounds__(256) k_qkv(const float* __restrict__ bqkv) {
    __shared__ __align__(16) float s_xT[E_][40];   // 32 rows + pad
    const int r0 = blockIdx.x * 32;
    const int cb = blockIdx.y * 128;
    const int tid = threadIdx.x;
    const int j   = tid & 127;
    const int rg  = tid >> 7;        // 0/1 -> rows rg*16 .. rg*16+15

    for (int i = tid; i < 32 * E_; i += 256) {
        int row = i >> 7;
        int e   = i & 127;
        s_xT[e][row] = g_agg1[(r0 + row) * E_ + e];
    }
    __syncthreads();

    const float bv = bqkv[cb + j];
    float acc[16];
#pragma unroll
    for (int i = 0; i < 16; i++) acc[i] = bv;

#pragma unroll 4
    for (int e = 0; e < E_; e++) {
        float w = g_WqkvT[e * QKV_ + cb + j];
#pragma unroll
        for (int i4 = 0; i4 < 4; i4++) {
            float4 x = *reinterpret_cast<const float4*>(&s_xT[e][rg * 16 + i4 * 4]);
            acc[i4 * 4 + 0] += x.x * w;
            acc[i4 * 4 + 1] += x.y * w;
            acc[i4 * 4 + 2] += x.z * w;
            acc[i4 * 4 + 3] += x.w * w;
        }
    }
#pragma unroll
    for (int i = 0; i < 16; i++)
        g_qkv[(r0 + rg * 16 + i) * QKV_ + cb + j] = acc[i];
}

// ---------------------------------------------------------------------------
// Kernel D: attention core.  block = 4 batches (32 qkv rows staged in smem),
// 256 threads: one per (bl, h, m).
// ---------------------------------------------------------------------------
__global__ void __launch_bounds__(256) k_attncore() {
    __shared__ __align__(16) float s_q[32][QKV_];   // 48 KB
    const int tid = threadIdx.x;
    const int b0  = blockIdx.x * 4;

    {
        const float4* src = reinterpret_cast<const float4*>(&g_qkv[b0 * M_ * QKV_]);
        float4* dst = reinterpret_cast<float4*>(&s_q[0][0]);
        for (int i = tid; i < 32 * QKV_ / 4; i += 256) dst[i] = src[i];
    }
    __syncthreads();

    const int bl = tid >> 6;
    const int h  = (tid >> 3) & 7;
    const int mm = tid & 7;
    const int qrow = bl * 8 + mm;
    const int hb = h * HD_;

    float4 q0 = *reinterpret_cast<const float4*>(&s_q[qrow][hb + 0]);
    float4 q1 = *reinterpret_cast<const float4*>(&s_q[qrow][hb + 4]);
    float4 q2 = *reinterpret_cast<const float4*>(&s_q[qrow][hb + 8]);
    float4 q3 = *reinterpret_cast<const float4*>(&s_q[qrow][hb + 12]);

    float s[M_];
    float mx = -1e30f;
#pragma unroll
    for (int n = 0; n < M_; n++) {
        const float* kp = &s_q[bl * 8 + n][E_ + hb];
        float4 k0 = *reinterpret_cast<const float4*>(kp + 0);
        float4 k1 = *reinterpret_cast<const float4*>(kp + 4);
        float4 k2 = *reinterpret_cast<const float4*>(kp + 8);
        float4 k3 = *reinterpret_cast<const float4*>(kp + 12);
        float d = q0.x*k0.x + q0.y*k0.y + q0.z*k0.z + q0.w*k0.w
                + q1.x*k1.x + q1.y*k1.y + q1.z*k1.z + q1.w*k1.w
                + q2.x*k2.x + q2.y*k2.y + q2.z*k2.z + q2.w*k2.w
                + q3.x*k3.x + q3.y*k3.y + q3.z*k3.z + q3.w*k3.w;
        s[n] = d * 0.25f;
        mx = fmaxf(mx, s[n]);
    }
    float sum = 0.f;
#pragma unroll
    for (int n = 0; n < M_; n++) { s[n] = __expf(s[n] - mx); sum += s[n]; }
    const float inv = 1.f / sum;

    float o[HD_];
#pragma unroll
    for (int t = 0; t < HD_; t++) o[t] = 0.f;
#pragma unroll
    for (int n = 0; n < M_; n++) {
        float p = s[n] * inv;
        const float* vp = &s_q[bl * 8 + n][2 * E_ + hb];
#pragma unroll
        for (int t = 0; t < HD_; t++) o[t] += p * vp[t];
    }

    float* op = &g_o[((b0 + bl) * M_ + mm) * E_ + hb];
#pragma unroll
    for (int t4 = 0; t4 < 4; t4++) {
        float4 v4 = make_float4(o[t4*4+0], o[t4*4+1], o[t4*4+2], o[t4*4+3]);
        *reinterpret_cast<float4*>(op + t4 * 4) = v4;
    }
}

// ---------------------------------------------------------------------------
// Kernel E: output projection GEMM [2048,128] @ [128,128], permuted store.
// grid = 128 row-tiles of 16; 256 threads = 128 cols x 2 rowgroups of 8.
// ---------------------------------------------------------------------------
__global__ void __launch_bounds__(256) k_oproj(const float* __restrict__ bo,
                                               float* __restrict__ out) {
    __shared__ __align__(16) float s_xT[E_][20];
    const int r0 = blockIdx.x * 16;
    const int tid = threadIdx.x;
    const int j   = tid & 127;
    const int rg  = tid >> 7;

    for (int i = tid; i < 16 * E_; i += 256) {
        int row = i >> 7;
        int e   = i & 127;
        s_xT[e][row] = g_o[(r0 + row) * E_ + e];
    }
    __syncthreads();

    const float bv = bo[j];
    float acc[8];
#pragma unroll
    for (int i = 0; i < 8; i++) acc[i] = bv;

#pragma unroll 4
    for (int e = 0; e < E_; e++) {
        float w = g_WoT[e * E_ + j];
        float4 x0 = *reinterpret_cast<const float4*>(&s_xT[e][rg * 8 + 0]);
        float4 x1 = *reinterpret_cast<const float4*>(&s_xT[e][rg * 8 + 4]);
        acc[0] += x0.x * w; acc[1] += x0.y * w; acc[2] += x0.z * w; acc[3] += x0.w * w;
        acc[4] += x1.x * w; acc[5] += x1.y * w; acc[6] += x1.z * w; acc[7] += x1.w * w;
    }
#pragma unroll
    for (int i = 0; i < 8; i++) {
        int r = r0 + rg * 8 + i;       // r = b*8 + m
        int b = r >> 3;
        int m = r & 7;
        out[m * (B_ * E_) + b * E_ + j] = acc[i];
    }
}

// ---------------------------------------------------------------------------
extern "C" void kernel_launch(void* const* d_in, const int* in_sizes, int n_in,
                              void* d_out, int out_size) {
    (void)in_sizes; (void)n_in; (void)out_size;
    const int*   node_idx    = (const int*)d_in[0];  (void)node_idx;
    const int*   mp_type_idx = (const int*)d_in[1];
    const int*   walks       = (const int*)d_in[2];
    const float* node_table  = (const float*)d_in[3];
    const float* fc1_b       = (const float*)d_in[4];
    const float* edge_table  = (const float*)d_in[5];
    const float* W_mp        = (const float*)d_in[6];
    const float* b_mp        = (const float*)d_in[7];
    const float* Wqkv        = (const float*)d_in[8];
    const float* bqkv        = (const float*)d_in[9];
    const float* Wo          = (const float*)d_in[10];
    const float* bo          = (const float*)d_in[11];
    float* out = (float*)d_out;

    k_transpose<<<(E_ * QKV_ + 255) / 256, 256>>>(Wqkv, Wo);
    k_gather<<<B_ * M_, E_>>>(walks, node_table, fc1_b, edge_table);
    dim3 gB(M_, B_ / 16);
    k_mplinear<<<gB, 256>>>(mp_type_idx, W_mp, b_mp);
    dim3 gQ(R_ / 32, 3);
    k_qkv<<<gQ, 256>>>(bqkv);
    k_attncore<<<B_ / 4, 256>>>();
    k_oproj<<<R_ / 16, 256>>>(bo, out);
}

// round 4
// speedup vs baseline: 1.4457x; 1.4457x over previous
#include <cuda_runtime.h>

#define B_   256
#define M_   8
#define L_   64
#define E_   128
#define H_   8
#define HD_  16
#define QKV_ 384
#define QP_  392          // padded qkv row stride (floats, 16B-aligned, bank-skewed)
#define XP_  12           // padded row count for transposed X tiles (16B-aligned)
#define R_   (B_ * M_)

// Scratch (no allocation allowed -> __device__ globals)
__device__ float g_agg0[R_ * E_];        // mean-fused walk aggregate, row = b*8+m
__device__ float g_agg1[R_ * E_];        // after per-metapath linear, row = b*8+m
__device__ float g_WqkvT[E_ * QKV_];     // Wqkv transposed: [e][j]
__device__ float g_WoT[E_ * E_];         // Wo transposed:   [e][j]

// ---------------------------------------------------------------------------
// Kernel T: transpose Wqkv [384][128] -> [128][384], Wo [128][128] -> [128][128]
// ---------------------------------------------------------------------------
__global__ void k_transpose(const float* __restrict__ Wqkv,
                            const float* __restrict__ Wo) {
    int tid = blockIdx.x * blockDim.x + threadIdx.x;
    if (tid < E_ * QKV_) {
        int j = tid / E_;
        int e = tid % E_;
        g_WqkvT[e * QKV_ + j] = Wqkv[j * E_ + e];
    }
    if (tid < E_ * E_) {
        int j = tid / E_;
        int e = tid % E_;
        g_WoT[e * E_ + j] = Wo[j * E_ + e];
    }
}

// ---------------------------------------------------------------------------
// Kernel A: gather + elementwise fuse + mean over walk steps
// block = (b*M + m), thread = e.
// ---------------------------------------------------------------------------
__global__ void k_gather(const int*   __restrict__ walks,
                         const float* __restrict__ node_table,
                         const float* __restrict__ fc1_b,
                         const float* __restrict__ edge_table) {
    __shared__ int s_idx[L_ * 3];
    const int bid = blockIdx.x;
    const int tid = threadIdx.x;
    const int base = bid * (L_ * 3);
    for (int i = tid; i < L_ * 3; i += E_) s_idx[i] = walks[base + i];
    __syncthreads();

    const float fb = fc1_b[tid];
    float acc = 0.f;
#pragma unroll 8
    for (int l = 0; l < L_; l++) {
        int n1 = s_idx[3 * l + 0];
        int n2 = s_idx[3 * l + 1];
        int et = s_idx[3 * l + 2];
        float a = node_table[n1 * E_ + tid] + fb;
        float b = node_table[n2 * E_ + tid] + fb;
        float c = edge_table[et * E_ + tid];
        acc += a * b * c;
    }
    g_agg0[bid * E_ + tid] = acc * (1.f / (float)L_);
}

// ---------------------------------------------------------------------------
// Kernel B: per-metapath linear.  block = (m, 8-batch tile); 128 threads.
// grid = 8 x 32 = 256 blocks.  X transposed in smem -> broadcast LDS.128.
// ---------------------------------------------------------------------------
__global__ void __launch_bounds__(128) k_mplinear(const int*   __restrict__ mp_type_idx,
                                                  const float* __restrict__ W_mp,
                                                  const float* __restrict__ b_mp) {
    __shared__ __align__(16) float s_xT[E_][XP_];   // 8 rows used
    const int m   = blockIdx.x;
    const int b0  = blockIdx.y * 8;
    const int tid = threadIdx.x;                    // output col

    for (int i = tid; i < 8 * E_; i += 128) {
        int row = i >> 7;
        int e   = i & 127;
        s_xT[e][row] = g_agg0[((b0 + row) * M_ + m) * E_ + e];
    }
    __syncthreads();

    const int mt = mp_type_idx[m];
    const float* W = W_mp + mt * (E_ * E_);
    const float bv = b_mp[mt * E_ + tid];

    float acc[8];
#pragma unroll
    for (int i = 0; i < 8; i++) acc[i] = bv;

#pragma unroll 8
    for (int e = 0; e < E_; e++) {
        float w = W[e * E_ + tid];
        float4 x0 = *reinterpret_cast<const float4*>(&s_xT[e][0]);
        float4 x1 = *reinterpret_cast<const float4*>(&s_xT[e][4]);
        acc[0] += x0.x * w; acc[1] += x0.y * w; acc[2] += x0.z * w; acc[3] += x0.w * w;
        acc[4] += x1.x * w; acc[5] += x1.y * w; acc[6] += x1.z * w; acc[7] += x1.w * w;
    }
#pragma unroll
    for (int i = 0; i < 8; i++)
        g_agg1[((b0 + i) * M_ + m) * E_ + tid] = acc[i];
}

// ---------------------------------------------------------------------------
// Kernel C: fused QKV + attention core + output projection.
// One batch per block; 384 threads; 256 blocks.
// ---------------------------------------------------------------------------
__global__ void __launch_bounds__(QKV_) k_attn(const float* __restrict__ bqkv,
                                               const float* __restrict__ bo,
                                               float* __restrict__ out) {
    __shared__ __align__(16) float s_xT[E_][XP_];   // x transposed: [e][m], 6 KB
    __shared__ __align__(16) float s_qkv[M_][QP_];  // 12.5 KB
    __shared__ __align__(16) float s_oT[E_][XP_];   // attn out transposed: [e][m], 6 KB

    const int tid = threadIdx.x;          // 0..383
    const int b   = blockIdx.x;

    // ---- stage x transposed ----
    for (int i = tid; i < M_ * E_; i += QKV_) {
        int m = i >> 7;
        int e = i & 127;
        s_xT[e][m] = g_agg1[b * (M_ * E_) + i];
    }
    __syncthreads();

    // ---- QKV: qkv[m][tid] = sum_e x[m][e] * WqkvT[e][tid] + bqkv[tid] ----
    {
        float acc[M_];
        const float bj = bqkv[tid];
#pragma unroll
        for (int m = 0; m < M_; m++) acc[m] = bj;

#pragma unroll 8
        for (int e = 0; e < E_; e++) {
            float w = g_WqkvT[e * QKV_ + tid];
            float4 x0 = *reinterpret_cast<const float4*>(&s_xT[e][0]);
            float4 x1 = *reinterpret_cast<const float4*>(&s_xT[e][4]);
            acc[0] += x0.x * w; acc[1] += x0.y * w; acc[2] += x0.z * w; acc[3] += x0.w * w;
            acc[4] += x1.x * w; acc[5] += x1.y * w; acc[6] += x1.z * w; acc[7] += x1.w * w;
        }
#pragma unroll
        for (int m = 0; m < M_; m++) s_qkv[m][tid] = acc[m];
    }
    __syncthreads();

    // ---- attention core: one thread per (h, m), 64 threads ----
    if (tid < H_ * M_) {
        const int h  = tid >> 3;
        const int mm = tid & 7;
        const int hb = h * HD_;

        float4 q0 = *reinterpret_cast<const float4*>(&s_qkv[mm][hb + 0]);
        float4 q1 = *reinterpret_cast<const float4*>(&s_qkv[mm][hb + 4]);
        float4 q2 = *reinterpret_cast<const float4*>(&s_qkv[mm][hb + 8]);
        float4 q3 = *reinterpret_cast<const float4*>(&s_qkv[mm][hb + 12]);

        float s[M_];
        float mx = -1e30f;
#pragma unroll
        for (int n = 0; n < M_; n++) {
            const float* kp = &s_qkv[n][E_ + hb];
            float4 k0 = *reinterpret_cast<const float4*>(kp + 0);
            float4 k1 = *reinterpret_cast<const float4*>(kp + 4);
            float4 k2 = *reinterpret_cast<const float4*>(kp + 8);
            float4 k3 = *reinterpret_cast<const float4*>(kp + 12);
            float d = q0.x*k0.x + q0.y*k0.y + q0.z*k0.z + q0.w*k0.w
                    + q1.x*k1.x + q1.y*k1.y + q1.z*k1.z + q1.w*k1.w
                    + q2.x*k2.x + q2.y*k2.y + q2.z*k2.z + q2.w*k2.w
                    + q3.x*k3.x + q3.y*k3.y + q3.z*k3.z + q3.w*k3.w;
            s[n] = d * 0.25f;
            mx = fmaxf(mx, s[n]);
        }
        float sum = 0.f;
#pragma unroll
        for (int n = 0; n < M_; n++) { s[n] = __expf(s[n] - mx); sum += s[n]; }
        const float inv = 1.f / sum;

        float o[HD_];
#pragma unroll
        for (int t = 0; t < HD_; t++) o[t] = 0.f;
#pragma unroll
        for (int n = 0; n < M_; n++) {
            float p = s[n] * inv;
            const float* vp = &s_qkv[n][2 * E_ + hb];
#pragma unroll
            for (int t = 0; t < HD_; t++) o[t] += p * vp[t];
        }
        // store transposed: s_oT[e][m]
#pragma unroll
        for (int t = 0; t < HD_; t++) s_oT[hb + t][mm] = o[t];
    }
    __syncthreads();

    // ---- output projection: j = tid%128, row group rg = tid/128 ----
    {
        const int j  = tid & 127;
        const int rg = tid >> 7;               // 0,1,2
        const int m0 = rg * 3;                 // rows m0 .. m0+nr-1
        const int nr = (rg == 2) ? 2 : 3;
        const float bv = bo[j];
        float acc[3] = {bv, bv, bv};

#pragma unroll 8
        for (int e = 0; e < E_; e++) {
            float w = g_WoT[e * E_ + j];
            acc[0] += s_oT[e][m0 + 0] * w;
            acc[1] += s_oT[e][m0 + 1] * w;
            if (rg < 2) acc[2] += s_oT[e][m0 + 2] * w;
        }
#pragma unroll
        for (int i = 0; i < 3; i++) {
            if (i < nr)
                out[(m0 + i) * (B_ * E_) + b * E_ + j] = acc[i];
        }
    }
}

// ---------------------------------------------------------------------------
extern "C" void kernel_launch(void* const* d_in, const int* in_sizes, int n_in,
                              void* d_out, int out_size) {
    (void)in_sizes; (void)n_in; (void)out_size;
    const int*   node_idx    = (const int*)d_in[0];  (void)node_idx;
    const int*   mp_type_idx = (const int*)d_in[1];
    const int*   walks       = (const int*)d_in[2];
    const float* node_table  = (const float*)d_in[3];
    const float* fc1_b       = (const float*)d_in[4];
    const float* edge_table  = (const float*)d_in[5];
    const float* W_mp        = (const float*)d_in[6];
    const float* b_mp        = (const float*)d_in[7];
    const float* Wqkv        = (const float*)d_in[8];
    const float* bqkv        = (const float*)d_in[9];
    const float* Wo          = (const float*)d_in[10];
    const float* bo          = (const float*)d_in[11];
    float* out = (float*)d_out;

    k_transpose<<<(E_ * QKV_ + 255) / 256, 256>>>(Wqkv, Wo);
    k_gather<<<B_ * M_, E_>>>(walks, node_table, fc1_b, edge_table);
    dim3 gB(M_, B_ / 8);
    k_mplinear<<<gB, 128>>>(mp_type_idx, W_mp, b_mp);
    k_attn<<<B_, QKV_>>>(bqkv, bo, out);
}

// round 5
// speedup vs baseline: 1.5083x; 1.0433x over previous
#include <cuda_runtime.h>

#define B_   256
#define M_   8
#define L_   64
#define E_   128
#define H_   8
#define HD_  16
#define QKV_ 384
#define QP_  392          // padded qkv row stride in smem
#define R_   (B_ * M_)    // 2048 rows

// Scratch (no allocation allowed -> __device__ globals)
__device__ float g_agg0[R_ * E_];        // mean-fused walk aggregate, row = b*8+m
__device__ float g_agg1[R_ * E_];        // after per-metapath linear, row = b*8+m
__device__ float g_qkv[R_ * QKV_];       // qkv rows
__device__ float g_WqkvT[E_ * QKV_];     // Wqkv transposed: [e][j]
__device__ float g_WoT[E_ * E_];         // Wo transposed:   [e][j]

// ---------------------------------------------------------------------------
// Kernel T: transpose Wqkv [384][128] -> [128][384], Wo [128][128] -> [128][128]
// ---------------------------------------------------------------------------
__global__ void k_transpose(const float* __restrict__ Wqkv,
                            const float* __restrict__ Wo) {
    int tid = blockIdx.x * blockDim.x + threadIdx.x;
    if (tid < E_ * QKV_) {
        int j = tid / E_;
        int e = tid % E_;
        g_WqkvT[e * QKV_ + j] = Wqkv[j * E_ + e];
    }
    if (tid < E_ * E_) {
        int j = tid / E_;
        int e = tid % E_;
        g_WoT[e * E_ + j] = Wo[j * E_ + e];
    }
}

// ---------------------------------------------------------------------------
// Kernel A: gather + elementwise fuse + mean over walk steps
// block = (b*M + m), thread = e.
// ---------------------------------------------------------------------------
__global__ void k_gather(const int*   __restrict__ walks,
                         const float* __restrict__ node_table,
                         const float* __restrict__ fc1_b,
                         const float* __restrict__ edge_table) {
    __shared__ int s_idx[L_ * 3];
    const int bid = blockIdx.x;
    const int tid = threadIdx.x;
    const int base = bid * (L_ * 3);
    for (int i = tid; i < L_ * 3; i += E_) s_idx[i] = walks[base + i];
    __syncthreads();

    const float fb = fc1_b[tid];
    float acc = 0.f;
#pragma unroll 8
    for (int l = 0; l < L_; l++) {
        int n1 = s_idx[3 * l + 0];
        int n2 = s_idx[3 * l + 1];
        int et = s_idx[3 * l + 2];
        float a = node_table[n1 * E_ + tid] + fb;
        float b = node_table[n2 * E_ + tid] + fb;
        float c = edge_table[et * E_ + tid];
        acc += a * b * c;
    }
    g_agg0[bid * E_ + tid] = acc * (1.f / (float)L_);
}

// ---------------------------------------------------------------------------
// Kernel B: per-metapath linear.  block = (m, 4-batch tile); 256 threads.
// grid = 8 x 64 = 512 blocks.  thread = (col, rowgroup of 2), 2 accumulators.
// 8-deep weight prefetch for MLP.
// ---------------------------------------------------------------------------
__global__ void __launch_bounds__(256) k_mplinear(const int*   __restrict__ mp_type_idx,
                                                  const float* __restrict__ W_mp,
                                                  const float* __restrict__ b_mp) {
    __shared__ __align__(16) float s_xT[E_][4];
    const int m   = blockIdx.x;
    const int b0  = blockIdx.y * 4;
    const int tid = threadIdx.x;
    const int j   = tid & 127;
    const int rg  = tid >> 7;          // rows rg*2 .. rg*2+1

    for (int i = tid; i < 4 * E_; i += 256) {
        int row = i >> 7;
        int e   = i & 127;
        s_xT[e][row] = g_agg0[((b0 + row) * M_ + m) * E_ + e];
    }
    __syncthreads();

    const int mt = mp_type_idx[m];
    const float* W = W_mp + mt * (E_ * E_);
    const float bv = b_mp[mt * E_ + j];

    float acc0 = bv, acc1 = bv;

    for (int ee = 0; ee < E_; ee += 8) {
        float w[8];
#pragma unroll
        for (int u = 0; u < 8; u++) w[u] = W[(ee + u) * E_ + j];
#pragma unroll
        for (int u = 0; u < 8; u++) {
            float2 x = *reinterpret_cast<const float2*>(&s_xT[ee + u][rg * 2]);
            acc0 += x.x * w[u];
            acc1 += x.y * w[u];
        }
    }
    g_agg1[((b0 + rg * 2 + 0) * M_ + m) * E_ + j] = acc0;
    g_agg1[((b0 + rg * 2 + 1) * M_ + m) * E_ + j] = acc1;
}

// ---------------------------------------------------------------------------
// Kernel C: QKV GEMM [2048,128] @ [128,384].
// tile = 8 rows x 128 cols; grid (256, 3) = 768 blocks; 256 threads =
// (col, rowgroup of 4); 4 accumulators; 8-deep weight prefetch.
// ---------------------------------------------------------------------------
__global__ void __launch_bounds__(256) k_qkv(const float* __restrict__ bqkv) {
    __shared__ __align__(16) float s_xT[E_][8];
    const int r0  = blockIdx.x * 8;
    const int cb  = blockIdx.y * 128;
    const int tid = threadIdx.x;
    const int j   = tid & 127;
    const int rg  = tid >> 7;          // rows rg*4 .. rg*4+3

    for (int i = tid; i < 8 * E_; i += 256) {
        int row = i >> 7;
        int e   = i & 127;
        s_xT[e][row] = g_agg1[(r0 + row) * E_ + e];
    }
    __syncthreads();

    const float bv = bqkv[cb + j];
    float acc[4] = {bv, bv, bv, bv};

    for (int ee = 0; ee < E_; ee += 8) {
        float w[8];
#pragma unroll
        for (int u = 0; u < 8; u++) w[u] = g_WqkvT[(ee + u) * QKV_ + cb + j];
#pragma unroll
        for (int u = 0; u < 8; u++) {
            float4 x = *reinterpret_cast<const float4*>(&s_xT[ee + u][rg * 4]);
            acc[0] += x.x * w[u];
            acc[1] += x.y * w[u];
            acc[2] += x.z * w[u];
            acc[3] += x.w * w[u];
        }
    }
#pragma unroll
    for (int i = 0; i < 4; i++)
        g_qkv[(r0 + rg * 4 + i) * QKV_ + cb + j] = acc[i];
}

// ---------------------------------------------------------------------------
// Kernel D: attention core + output projection.  One batch per block;
// 256 threads; grid 256.
// ---------------------------------------------------------------------------
__global__ void __launch_bounds__(256) k_attnoproj(const float* __restrict__ bo,
                                                   float* __restrict__ out) {
    __shared__ __align__(16) float s_q[M_][QP_];    // 12.5 KB
    __shared__ __align__(16) float s_oT[E_][8];     // attn out transposed [e][m], 4 KB

    const int tid = threadIdx.x;
    const int b   = blockIdx.x;

    // stage qkv rows for this batch (contiguous 12 KB)
    {
        const float4* src = reinterpret_cast<const float4*>(&g_qkv[b * M_ * QKV_]);
        for (int i = tid; i < M_ * QKV_ / 4; i += 256) {
            int m = i / (QKV_ / 4);
            int c = i % (QKV_ / 4);
            *reinterpret_cast<float4*>(&s_q[m][c * 4]) = src[i];
        }
    }
    __syncthreads();

    // attention core: one thread per (h, m)
    if (tid < H_ * M_) {
        const int h  = tid >> 3;
        const int mm = tid & 7;
        const int hb = h * HD_;

        float4 q0 = *reinterpret_cast<const float4*>(&s_q[mm][hb + 0]);
        float4 q1 = *reinterpret_cast<const float4*>(&s_q[mm][hb + 4]);
        float4 q2 = *reinterpret_cast<const float4*>(&s_q[mm][hb + 8]);
        float4 q3 = *reinterpret_cast<const float4*>(&s_q[mm][hb + 12]);

        float s[M_];
        float mx = -1e30f;
#pragma unroll
        for (int n = 0; n < M_; n++) {
            const float* kp = &s_q[n][E_ + hb];
            float4 k0 = *reinterpret_cast<const float4*>(kp + 0);
            float4 k1 = *reinterpret_cast<const float4*>(kp + 4);
            float4 k2 = *reinterpret_cast<const float4*>(kp + 8);
            float4 k3 = *reinterpret_cast<const float4*>(kp + 12);
            float d = q0.x*k0.x + q0.y*k0.y + q0.z*k0.z + q0.w*k0.w
                    + q1.x*k1.x + q1.y*k1.y + q1.z*k1.z + q1.w*k1.w
                    + q2.x*k2.x + q2.y*k2.y + q2.z*k2.z + q2.w*k2.w
                    + q3.x*k3.x + q3.y*k3.y + q3.z*k3.z + q3.w*k3.w;
            s[n] = d * 0.25f;
            mx = fmaxf(mx, s[n]);
        }
        float sum = 0.f;
#pragma unroll
        for (int n = 0; n < M_; n++) { s[n] = __expf(s[n] - mx); sum += s[n]; }
        const float inv = 1.f / sum;

        float o[HD_];
#pragma unroll
        for (int t = 0; t < HD_; t++) o[t] = 0.f;
#pragma unroll
        for (int n = 0; n < M_; n++) {
            float p = s[n] * inv;
            const float* vp = &s_q[n][2 * E_ + hb];
#pragma unroll
            for (int t = 0; t < HD_; t++) o[t] += p * vp[t];
        }
#pragma unroll
        for (int t = 0; t < HD_; t++) s_oT[hb + t][mm] = o[t];
    }
    __syncthreads();

    // output projection: thread = (col, rowgroup of 4), 8-deep prefetch
    {
        const int j  = tid & 127;
        const int rg = tid >> 7;           // rows rg*4 .. rg*4+3
        const float bv = bo[j];
        float acc[4] = {bv, bv, bv, bv};

        for (int ee = 0; ee < E_; ee += 8) {
            float w[8];
#pragma unroll
            for (int u = 0; u < 8; u++) w[u] = g_WoT[(ee + u) * E_ + j];
#pragma unroll
            for (int u = 0; u < 8; u++) {
                float4 x = *reinterpret_cast<const float4*>(&s_oT[ee + u][rg * 4]);
                acc[0] += x.x * w[u];
                acc[1] += x.y * w[u];
                acc[2] += x.z * w[u];
                acc[3] += x.w * w[u];
            }
        }
#pragma unroll
        for (int i = 0; i < 4; i++) {
            int m = rg * 4 + i;
            out[m * (B_ * E_) + b * E_ + j] = acc[i];
        }
    }
}

// ---------------------------------------------------------------------------
extern "C" void kernel_launch(void* const* d_in, const int* in_sizes, int n_in,
                              void* d_out, int out_size) {
    (void)in_sizes; (void)n_in; (void)out_size;
    const int*   node_idx    = (const int*)d_in[0];  (void)node_idx;
    const int*   mp_type_idx = (const int*)d_in[1];
    const int*   walks       = (const int*)d_in[2];
    const float* node_table  = (const float*)d_in[3];
    const float* fc1_b       = (const float*)d_in[4];
    const float* edge_table  = (const float*)d_in[5];
    const float* W_mp        = (const float*)d_in[6];
    const float* b_mp        = (const float*)d_in[7];
    const float* Wqkv        = (const float*)d_in[8];
    const float* bqkv        = (const float*)d_in[9];
    const float* Wo          = (const float*)d_in[10];
    const float* bo          = (const float*)d_in[11];
    float* out = (float*)d_out;

    k_transpose<<<(E_ * QKV_ + 255) / 256, 256>>>(Wqkv, Wo);
    k_gather<<<B_ * M_, E_>>>(walks, node_table, fc1_b, edge_table);
    dim3 gB(M_, B_ / 4);
    k_mplinear<<<gB, 256>>>(mp_type_idx, W_mp, b_mp);
    dim3 gQ(R_ / 8, 3);
    k_qkv<<<gQ, 256>>>(bqkv);
    k_attnoproj<<<B_, 256>>>(bo, out);
}